// round 1
// baseline (speedup 1.0000x reference)
#include <cuda_runtime.h>

// DCT band decomposition: x[16,3,512,512] f32 -> (low, mid, high) each same shape,
// concatenated into d_out. One thread owns one 8x8 block, fully register-resident.

namespace {
constexpr int BATCH = 16, CHAN = 3, H = 512, W = 512;
constexpr int NPIX = BATCH * CHAN * H * W;       // 12582912
constexpr int NBLOCKS = BATCH * CHAN * (H / 8) * (W / 8); // 196608
constexpr int TPB = 128;
}

// Orthonormal 8-point DCT-II matrix, hardcoded so it lives in constant bank
// and folds into FFMA c[bank] operands after full unrolling.
#define A4 0.3535533905932738f
#define C1 0.4903926402016152f
#define C2 0.4619397662556434f
#define C3 0.4157348061512726f
#define C5 0.2777851165098011f
#define C6 0.1913417161825449f
#define C7 0.0975451610080641f

__constant__ float cD[8][8] = {
    { A4,  A4,  A4,  A4,  A4,  A4,  A4,  A4},
    { C1,  C3,  C5,  C7, -C7, -C5, -C3, -C1},
    { C2,  C6, -C6, -C2, -C2, -C6,  C6,  C2},
    { C3, -C7, -C1, -C5,  C5,  C1,  C7, -C3},
    { A4, -A4, -A4,  A4,  A4, -A4, -A4,  A4},
    { C5, -C1,  C7,  C3, -C3, -C7,  C1, -C5},
    { C6, -C2,  C2, -C6, -C6,  C2, -C2,  C6},
    { C7, -C5,  C3, -C1,  C1, -C3,  C5, -C7}
};

// Zigzag band membership (compile-time predicates):
//   low : zz < 21   <=>  k+l <= 5
//   mid : 21<=zz<42 <=>  6 <= k+l <= 8, excluding (k,l)=(1,7)
//   high: everything else (computed as residual: x - low_u - mid_u)
template <int BAND>
__device__ __forceinline__ bool in_band(int k, int l) {
    const int s = k + l;
    if (BAND == 0) return s <= 5;
    else           return (s >= 6 && s <= 8) && !(k == 1 && l == 7);
}

// Inverse-DCT one masked band, row-streamed (no full 8x8 temp), store scaled
// result and subtract the unscaled band from X (residual accumulation).
template <int BAND>
__device__ __forceinline__ void reconstruct_band(
    const float C[8][8], float X[8][8], float scale, float* __restrict__ dst)
{
#pragma unroll
    for (int m = 0; m < 8; m++) {
        float yr[8];
#pragma unroll
        for (int l = 0; l < 8; l++) {
            float s = 0.0f;
#pragma unroll
            for (int k = 0; k < 8; k++) {
                if (in_band<BAND>(k, l))   // k,l constants after unroll -> folded
                    s = fmaf(cD[k][m], C[k][l], s);
            }
            yr[l] = s;
        }
        float orow[8];
#pragma unroll
        for (int n = 0; n < 8; n++) {
            float s = 0.0f;
#pragma unroll
            for (int l = 0; l < 8; l++)
                s = fmaf(yr[l], cD[l][n], s);
            orow[n] = s;
            X[m][n] -= s;
        }
        float4 o0 = make_float4(orow[0] * scale, orow[1] * scale,
                                orow[2] * scale, orow[3] * scale);
        float4 o1 = make_float4(orow[4] * scale, orow[5] * scale,
                                orow[6] * scale, orow[7] * scale);
        *reinterpret_cast<float4*>(dst + m * W)     = o0;
        *reinterpret_cast<float4*>(dst + m * W + 4) = o1;
    }
}

__global__ void __launch_bounds__(TPB, 2)
dct_decomp_kernel(const float* __restrict__ x,
                  const float* __restrict__ band_scale,
                  float* __restrict__ out)
{
    const int tid = blockIdx.x * TPB + threadIdx.x;   // grid sized exactly
    const int bw = tid & 63;          // block col (W/8 = 64)
    const int bh = (tid >> 6) & 63;   // block row
    const int bc = tid >> 12;         // fused batch*chan 0..47

    const size_t base = ((size_t)bc * H + (size_t)bh * 8) * W + (size_t)bw * 8;
    const float* src = x + base;

    const float s0 = __ldg(band_scale + 0);
    const float s1 = __ldg(band_scale + 1);
    const float s2 = __ldg(band_scale + 2);

    // ---- Load 8x8 block (16 independent LDG.128, front-batched) ----
    float X[8][8];
#pragma unroll
    for (int r = 0; r < 8; r++) {
        float4 a = *reinterpret_cast<const float4*>(src + (size_t)r * W);
        float4 b = *reinterpret_cast<const float4*>(src + (size_t)r * W + 4);
        X[r][0] = a.x; X[r][1] = a.y; X[r][2] = a.z; X[r][3] = a.w;
        X[r][4] = b.x; X[r][5] = b.y; X[r][6] = b.z; X[r][7] = b.w;
    }

    // ---- Forward 2D DCT: C = D * X * D^T ----
    float C[8][8];
#pragma unroll
    for (int k = 0; k < 8; k++) {      // tmp = D * X  (stored into C)
#pragma unroll
        for (int t = 0; t < 8; t++) {
            float s = 0.0f;
#pragma unroll
            for (int m = 0; m < 8; m++)
                s = fmaf(cD[k][m], X[m][t], s);
            C[k][t] = s;
        }
    }
#pragma unroll
    for (int k = 0; k < 8; k++) {      // C = tmp * D^T, in place row-wise
        float row[8];
#pragma unroll
        for (int t = 0; t < 8; t++) row[t] = C[k][t];
#pragma unroll
        for (int l = 0; l < 8; l++) {
            float s = 0.0f;
#pragma unroll
            for (int t = 0; t < 8; t++)
                s = fmaf(row[t], cD[l][t], s);
            C[k][l] = s;
        }
    }

    // ---- Band reconstructions ----
    float* dst_low  = out + base;
    float* dst_mid  = out + (size_t)NPIX + base;
    float* dst_high = out + 2 * (size_t)NPIX + base;

    reconstruct_band<0>(C, X, s0, dst_low);   // X -= low_u
    reconstruct_band<1>(C, X, s1, dst_mid);   // X -= mid_u

    // high = residual * s2
#pragma unroll
    for (int m = 0; m < 8; m++) {
        float4 o0 = make_float4(X[m][0] * s2, X[m][1] * s2,
                                X[m][2] * s2, X[m][3] * s2);
        float4 o1 = make_float4(X[m][4] * s2, X[m][5] * s2,
                                X[m][6] * s2, X[m][7] * s2);
        *reinterpret_cast<float4*>(dst_high + m * W)     = o0;
        *reinterpret_cast<float4*>(dst_high + m * W + 4) = o1;
    }
}

extern "C" void kernel_launch(void* const* d_in, const int* in_sizes, int n_in,
                              void* d_out, int out_size)
{
    const float* x  = (const float*)d_in[0];
    const float* bs = (const float*)d_in[1];
    float* out = (float*)d_out;

    const int grid = NBLOCKS / TPB;   // 1536
    dct_decomp_kernel<<<grid, TPB>>>(x, bs, out);
}

// round 2
// speedup vs baseline: 1.2354x; 1.2354x over previous
#include <cuda_runtime.h>

// DCT band decomposition: x[16,3,512,512] f32 -> (low, mid, high) concatenated.
// One thread owns one 8x8 block; DCT matrix folded to FFMA immediates.

namespace {
constexpr int BATCH = 16, CHAN = 3, H = 512, W = 512;
constexpr int NPIX = BATCH * CHAN * H * W;                 // 12582912
constexpr int NBLOCKS = BATCH * CHAN * (H / 8) * (W / 8);  // 196608
constexpr int TPB = 128;
}

// Orthonormal 8-point DCT-II matrix as a constexpr function so that, after
// full unroll, every access is a compile-time literal -> FFMA imm-form
// (rt_SMSP=1, no LDC; Blackwell removed cbank-as-operand).
__host__ __device__ constexpr float Dv(int k, int t) {
    constexpr float A4 = 0.3535533905932738f;
    constexpr float C1 = 0.4903926402016152f;
    constexpr float C2 = 0.4619397662556434f;
    constexpr float C3 = 0.4157348061512726f;
    constexpr float C5 = 0.2777851165098011f;
    constexpr float C6 = 0.1913417161825449f;
    constexpr float C7 = 0.0975451610080641f;
    constexpr float m[8][8] = {
        { A4,  A4,  A4,  A4,  A4,  A4,  A4,  A4},
        { C1,  C3,  C5,  C7, -C7, -C5, -C3, -C1},
        { C2,  C6, -C6, -C2, -C2, -C6,  C6,  C2},
        { C3, -C7, -C1, -C5,  C5,  C1,  C7, -C3},
        { A4, -A4, -A4,  A4,  A4, -A4, -A4,  A4},
        { C5, -C1,  C7,  C3, -C3, -C7,  C1, -C5},
        { C6, -C2,  C2, -C6, -C6,  C2, -C2,  C6},
        { C7, -C5,  C3, -C1,  C1, -C3,  C5, -C7}
    };
    return m[k][t];
}

// Zigzag band membership (zz<21 | 21<=zz<42 | zz>=42), compile-time:
//   low : k+l <= 5
//   mid : 6 <= k+l <= 8, excluding (1,7)
//   high: the rest
__host__ __device__ constexpr bool in_band(int band, int k, int l) {
    const int s = k + l;
    const bool low = (s <= 5);
    const bool mid = (s >= 6 && s <= 8) && !(k == 1 && l == 7);
    if (band == 0) return low;
    if (band == 1) return mid;
    return !low && !mid;
}

// Does column l contain any in-band coefficient? (prunes 2nd-stage FMAs)
__host__ __device__ constexpr bool col_active(int band, int l) {
    bool a = false;
    for (int k = 0; k < 8; k++)
        if (in_band(band, k, l)) a = true;
    return a;
}

// Masked inverse DCT of one band, row-streamed: out = D^T (M ∘ C) D * scale.
template <int BAND>
__device__ __forceinline__ void band_idct(const float C[8][8], float scale,
                                          float* __restrict__ dst)
{
#pragma unroll
    for (int m = 0; m < 8; m++) {
        float yr[8];
#pragma unroll
        for (int l = 0; l < 8; l++) {
            float s = 0.0f;
#pragma unroll
            for (int k = 0; k < 8; k++)
                if (in_band(BAND, k, l))
                    s = fmaf(C[k][l], Dv(k, m), s);
            yr[l] = s * scale;          // fold band scale here (fewer muls)
        }
        float o[8];
#pragma unroll
        for (int n = 0; n < 8; n++) {
            float s = 0.0f;
#pragma unroll
            for (int l = 0; l < 8; l++)
                if (col_active(BAND, l))
                    s = fmaf(yr[l], Dv(l, n), s);
            o[n] = s;
        }
        *reinterpret_cast<float4*>(dst + m * W) =
            make_float4(o[0], o[1], o[2], o[3]);
        *reinterpret_cast<float4*>(dst + m * W + 4) =
            make_float4(o[4], o[5], o[6], o[7]);
    }
}

__global__ void __launch_bounds__(TPB, 4)
dct_decomp_kernel(const float* __restrict__ x,
                  const float* __restrict__ band_scale,
                  float* __restrict__ out)
{
    const int tid = blockIdx.x * TPB + threadIdx.x;   // grid sized exactly
    const int bw = tid & 63;          // block col (W/8 = 64)
    const int bh = (tid >> 6) & 63;   // block row
    const int bc = tid >> 12;         // fused batch*chan 0..47

    const size_t base = ((size_t)bc * H + (size_t)bh * 8) * W + (size_t)bw * 8;
    const float* src = x + base;

    const float s0 = __ldg(band_scale + 0);
    const float s1 = __ldg(band_scale + 1);
    const float s2 = __ldg(band_scale + 2);

    // ---- Load 8x8 block (16 independent LDG.128, front-batched) ----
    float X[8][8];
#pragma unroll
    for (int r = 0; r < 8; r++) {
        float4 a = *reinterpret_cast<const float4*>(src + (size_t)r * W);
        float4 b = *reinterpret_cast<const float4*>(src + (size_t)r * W + 4);
        X[r][0] = a.x; X[r][1] = a.y; X[r][2] = a.z; X[r][3] = a.w;
        X[r][4] = b.x; X[r][5] = b.y; X[r][6] = b.z; X[r][7] = b.w;
    }

    // ---- Forward 2D DCT in place: X <- D X D^T ----
    // Column pass: X[:,t] <- D * X[:,t]
#pragma unroll
    for (int t = 0; t < 8; t++) {
        float tmp[8];
#pragma unroll
        for (int k = 0; k < 8; k++) {
            float s = 0.0f;
#pragma unroll
            for (int m = 0; m < 8; m++)
                s = fmaf(X[m][t], Dv(k, m), s);
            tmp[k] = s;
        }
#pragma unroll
        for (int k = 0; k < 8; k++) X[k][t] = tmp[k];
    }
    // Row pass: X[k,:] <- X[k,:] * D^T
#pragma unroll
    for (int k = 0; k < 8; k++) {
        float tmp[8];
#pragma unroll
        for (int l = 0; l < 8; l++) {
            float s = 0.0f;
#pragma unroll
            for (int t = 0; t < 8; t++)
                s = fmaf(X[k][t], Dv(l, t), s);
            tmp[l] = s;
        }
#pragma unroll
        for (int l = 0; l < 8; l++) X[k][l] = tmp[l];
    }

    // ---- Three masked inverse DCTs ----
    band_idct<0>(X, s0, out + base);
    band_idct<1>(X, s1, out + (size_t)NPIX + base);
    band_idct<2>(X, s2, out + 2 * (size_t)NPIX + base);
}

extern "C" void kernel_launch(void* const* d_in, const int* in_sizes, int n_in,
                              void* d_out, int out_size)
{
    const float* x  = (const float*)d_in[0];
    const float* bs = (const float*)d_in[1];
    float* out = (float*)d_out;

    const int grid = NBLOCKS / TPB;   // 1536
    dct_decomp_kernel<<<grid, TPB>>>(x, bs, out);
}